// round 2
// baseline (speedup 1.0000x reference)
#include <cuda_runtime.h>
#include <math.h>

#define N 384
#define D 128
#define NWARP (N / 32)

__device__ double g_acc_trans;
__device__ double g_acc_hard;

__global__ void rnc_init_kernel() {
    g_acc_trans = 0.0;
    g_acc_hard = 0.0;
}

__global__ __launch_bounds__(N) void rnc_main_kernel(
    const float* __restrict__ feat,   // [N, D]
    const float* __restrict__ rgreen, // [N, 3]
    const float* __restrict__ rred,   // [N, 3]
    const float* __restrict__ trans,  // [N, 3]
    const int*   __restrict__ sym)    // [N, 1]
{
    __shared__ float fi[D];
    __shared__ float l_sh[N];
    __shared__ float e_sh[N];
    __shared__ float td_sh[N];
    __shared__ float rd_sh[N];
    __shared__ float redf[NWARP];
    __shared__ double redt[NWARP];
    __shared__ double redh[NWARP];

    const int i = blockIdx.x;
    const int j = threadIdx.x;

    // ---- stage row-i feature vector in shared ----
    if (j < D) fi[j] = feat[i * D + j];
    __syncthreads();

    // ---- feature squared distance: sq = ||f_i - f_j||^2 ----
    float sq = 0.f;
    {
        const float4* fj4 = reinterpret_cast<const float4*>(feat + j * D);
        const float4* fi4 = reinterpret_cast<const float4*>(fi);
        #pragma unroll 8
        for (int c = 0; c < D / 4; c++) {
            float4 a = fi4[c];
            float4 b = fj4[c];
            float d0 = a.x - b.x, d1 = a.y - b.y, d2 = a.z - b.z, d3 = a.w - b.w;
            sq = fmaf(d0, d0, sq);
            sq = fmaf(d1, d1, sq);
            sq = fmaf(d2, d2, sq);
            sq = fmaf(d3, d3, sq);
        }
    }
    float nrm   = (sq > 0.f) ? sqrtf(sq) : 0.f;   // zero-safe norm (matches reference)
    float logit = -nrm * 0.5f;                    // / TEMPERATURE(=2)

    // ---- trans smooth-L1 (beta=1), mean over 3 coords ----
    float tdv;
    {
        float s = 0.f;
        #pragma unroll
        for (int c = 0; c < 3; c++) {
            float d  = trans[i * 3 + c] - trans[j * 3 + c];  // row-i reads are warp-broadcast
            float ad = fabsf(d);
            s += (ad < 1.0f) ? 0.5f * d * d : ad - 0.5f;
        }
        tdv = s * (1.0f / 3.0f);
    }

    // ---- rot cosine diffs + sym gating ----
    float rdv;
    {
        const float EPSC = 1e-8f;
        float gi0 = rgreen[i*3+0], gi1 = rgreen[i*3+1], gi2 = rgreen[i*3+2];
        float gj0 = rgreen[j*3+0], gj1 = rgreen[j*3+1], gj2 = rgreen[j*3+2];
        float ngi = fmaxf(sqrtf(gi0*gi0 + gi1*gi1 + gi2*gi2), EPSC);
        float ngj = fmaxf(sqrtf(gj0*gj0 + gj1*gj1 + gj2*gj2), EPSC);
        float gcos = (gi0*gj0 + gi1*gj1 + gi2*gj2) / (ngi * ngj);
        float gd = 1.0f - gcos;

        float ri0 = rred[i*3+0], ri1 = rred[i*3+1], ri2 = rred[i*3+2];
        float rj0 = rred[j*3+0], rj1 = rred[j*3+1], rj2 = rred[j*3+2];
        float nri = fmaxf(sqrtf(ri0*ri0 + ri1*ri1 + ri2*ri2), EPSC);
        float nrj = fmaxf(sqrtf(rj0*rj0 + rj1*rj1 + rj2*rj2), EPSC);
        float rcos = (ri0*rj0 + ri1*rj1 + ri2*rj2) / (nri * nrj);
        float rdd = 1.0f - rcos;

        bool psym = (sym[i] == 1) || (sym[j] == 1);
        rdv = psym ? gd : gd + rdd;
    }

    // ---- row max of logits (mathematically 0; computed for fidelity) ----
    float m = logit;
    #pragma unroll
    for (int o = 16; o; o >>= 1) m = fmaxf(m, __shfl_xor_sync(0xFFFFFFFFu, m, o));
    if ((j & 31) == 0) redf[j >> 5] = m;
    __syncthreads();
    if (j == 0) {
        float mm = redf[0];
        #pragma unroll
        for (int w = 1; w < NWARP; w++) mm = fmaxf(mm, redf[w]);
        redf[0] = mm;
    }
    __syncthreads();
    float rowmax = redf[0];

    float l = logit - rowmax;
    l_sh[j]  = l;
    e_sh[j]  = (j == i) ? 0.f : expf(l);  // zero diag weight == offdiag einsum
    td_sh[j] = tdv;
    rd_sh[j] = rdv;
    __syncthreads();

    // ---- O(n^2) per-row masked denominators; k-reads are warp-uniform broadcasts ----
    double pos_t = 0.0, pos_h = 0.0;
    if (j != i) {
        const float tij = tdv;
        const float rij = rdv;
        float dent = 0.f, denh = 0.f;
        #pragma unroll 4
        for (int k = 0; k < N; k++) {
            float tk = td_sh[k];
            float rk = rd_sh[k];
            float ek = e_sh[k];
            float mt = (tij <= tk) ? ek : 0.f;
            dent += mt;
            denh += (rij <= rk) ? mt : 0.f;
        }
        pos_t = (double)(l - logf(dent + 1e-7f));
        pos_h = (double)(l - logf(denh + 1e-7f));
    }

    // ---- block reduction (double) + global atomics ----
    #pragma unroll
    for (int o = 16; o; o >>= 1) {
        pos_t += __shfl_xor_sync(0xFFFFFFFFu, pos_t, o);
        pos_h += __shfl_xor_sync(0xFFFFFFFFu, pos_h, o);
    }
    if ((j & 31) == 0) { redt[j >> 5] = pos_t; redh[j >> 5] = pos_h; }
    __syncthreads();
    if (j == 0) {
        double at = 0.0, ah = 0.0;
        #pragma unroll
        for (int w = 0; w < NWARP; w++) { at += redt[w]; ah += redh[w]; }
        atomicAdd(&g_acc_trans, at);
        atomicAdd(&g_acc_hard, ah);
    }
}

__global__ void rnc_fin_kernel(float* __restrict__ out) {
    const double denom = (double)N * (double)(N - 1);
    double loss_hard  = -g_acc_hard  / denom;
    double loss_trans = -g_acc_trans / denom;
    out[0] = (float)(loss_hard + 0.5 * loss_trans);
}

extern "C" void kernel_launch(void* const* d_in, const int* in_sizes, int n_in,
                              void* d_out, int out_size) {
    const float* feat   = (const float*)d_in[0];
    const float* rgreen = (const float*)d_in[1];
    const float* rred   = (const float*)d_in[2];
    const float* trans  = (const float*)d_in[3];
    const int*   sym    = (const int*)d_in[4];
    float* out = (float*)d_out;

    rnc_init_kernel<<<1, 1>>>();
    rnc_main_kernel<<<N, N>>>(feat, rgreen, rred, trans, sym);
    rnc_fin_kernel<<<1, 1>>>(out);
}

// round 3
// speedup vs baseline: 1.5327x; 1.5327x over previous
#include <cuda_runtime.h>
#include <math.h>

#define N 384
#define D 128
#define NWARP (N / 32)
#define FULL 0xFFFFFFFFu

// Persistent accumulators. Zero-initialized at load; the last block resets them
// to zero after finalizing, so every invocation (correctness run + each graph
// replay) starts from a clean state. Deterministic.
__device__ double   g_acc_trans = 0.0;
__device__ double   g_acc_hard  = 0.0;
__device__ unsigned g_done      = 0u;

__global__ __launch_bounds__(N) void rnc_main_kernel(
    const float* __restrict__ feat,   // [N, D]
    const float* __restrict__ rgreen, // [N, 3]
    const float* __restrict__ rred,   // [N, 3]
    const float* __restrict__ trans,  // [N, 3]
    const int*   __restrict__ sym,    // [N, 1]
    float*       __restrict__ out)
{
    __shared__ __align__(16) float fi[D];
    __shared__ __align__(16) float td_sh[N];
    __shared__ __align__(16) float rd_sh[N];
    __shared__ __align__(16) float e_sh[N];
    __shared__ float  redf[NWARP];
    __shared__ double redt[NWARP];
    __shared__ double redh[NWARP];

    const int i    = blockIdx.x;
    const int j    = threadIdx.x;
    const int lane = j & 31;
    const int w    = j >> 5;

    // ---- stage row-i feature vector in shared (coalesced) ----
    if (j < D / 4)
        reinterpret_cast<float4*>(fi)[j] =
            reinterpret_cast<const float4*>(feat + i * D)[j];
    __syncthreads();

    // ---- feature squared distance, warp-cooperative & coalesced ----
    // Warp w owns rows [32w, 32w+32). For each row r, all 32 lanes load one
    // float4 of that row (512B coalesced), reduce, and lane r keeps the result
    // (row 32w+r == that lane's own j).
    float sq = 0.f;
    {
        const int rowbase = w * 32;
        const float4 a = reinterpret_cast<const float4*>(fi)[lane];
        #pragma unroll 4
        for (int r = 0; r < 32; r++) {
            float4 b = reinterpret_cast<const float4*>(feat + (rowbase + r) * D)[lane];
            float d0 = a.x - b.x, d1 = a.y - b.y, d2 = a.z - b.z, d3 = a.w - b.w;
            float p = d0 * d0;
            p = fmaf(d1, d1, p);
            p = fmaf(d2, d2, p);
            p = fmaf(d3, d3, p);
            #pragma unroll
            for (int o = 16; o; o >>= 1) p += __shfl_xor_sync(FULL, p, o);
            if (lane == r) sq = p;
        }
    }
    float nrm   = (sq > 0.f) ? sqrtf(sq) : 0.f;   // zero-safe norm (matches reference)
    float logit = -nrm * 0.5f;                    // / TEMPERATURE(=2)

    // ---- trans smooth-L1 (beta=1), mean over 3 coords ----
    float tdv;
    {
        float s = 0.f;
        #pragma unroll
        for (int c = 0; c < 3; c++) {
            float d  = trans[i * 3 + c] - trans[j * 3 + c];  // i-reads broadcast
            float ad = fabsf(d);
            s += (ad < 1.0f) ? 0.5f * d * d : ad - 0.5f;
        }
        tdv = s * (1.0f / 3.0f);
    }

    // ---- rot cosine diffs + sym gating ----
    float rdv;
    {
        const float EPSC = 1e-8f;
        float gi0 = rgreen[i*3+0], gi1 = rgreen[i*3+1], gi2 = rgreen[i*3+2];
        float gj0 = rgreen[j*3+0], gj1 = rgreen[j*3+1], gj2 = rgreen[j*3+2];
        float ngi = fmaxf(sqrtf(gi0*gi0 + gi1*gi1 + gi2*gi2), EPSC);
        float ngj = fmaxf(sqrtf(gj0*gj0 + gj1*gj1 + gj2*gj2), EPSC);
        float gd  = 1.0f - (gi0*gj0 + gi1*gj1 + gi2*gj2) / (ngi * ngj);

        float ri0 = rred[i*3+0], ri1 = rred[i*3+1], ri2 = rred[i*3+2];
        float rj0 = rred[j*3+0], rj1 = rred[j*3+1], rj2 = rred[j*3+2];
        float nri = fmaxf(sqrtf(ri0*ri0 + ri1*ri1 + ri2*ri2), EPSC);
        float nrj = fmaxf(sqrtf(rj0*rj0 + rj1*rj1 + rj2*rj2), EPSC);
        float rdd = 1.0f - (ri0*rj0 + ri1*rj1 + ri2*rj2) / (nri * nrj);

        bool psym = (sym[i] == 1) || (sym[j] == 1);
        rdv = psym ? gd : gd + rdd;
    }

    // ---- row max of logits (mathematically 0; kept for fidelity) ----
    float m = logit;
    #pragma unroll
    for (int o = 16; o; o >>= 1) m = fmaxf(m, __shfl_xor_sync(FULL, m, o));
    if (lane == 0) redf[w] = m;
    __syncthreads();
    if (j == 0) {
        float mm = redf[0];
        #pragma unroll
        for (int ww = 1; ww < NWARP; ww++) mm = fmaxf(mm, redf[ww]);
        redf[0] = mm;
    }
    __syncthreads();
    float rowmax = redf[0];

    float l = logit - rowmax;
    td_sh[j] = tdv;
    rd_sh[j] = rdv;
    e_sh[j]  = (j == i) ? 0.f : expf(l);  // zero diag weight == offdiag einsum
    __syncthreads();

    // ---- O(n^2) per-row masked denominators, float4-vectorized broadcasts ----
    double pos_t = 0.0, pos_h = 0.0;
    if (j != i) {
        const float tij = tdv;
        const float rij = rdv;
        const float4* td4 = reinterpret_cast<const float4*>(td_sh);
        const float4* rd4 = reinterpret_cast<const float4*>(rd_sh);
        const float4* e4  = reinterpret_cast<const float4*>(e_sh);
        float dent = 0.f, denh = 0.f;
        #pragma unroll 2
        for (int k4 = 0; k4 < N / 4; k4++) {
            float4 tk = td4[k4];
            float4 rk = rd4[k4];
            float4 ek = e4[k4];
            float m0 = (tij <= tk.x) ? ek.x : 0.f;
            float m1 = (tij <= tk.y) ? ek.y : 0.f;
            float m2 = (tij <= tk.z) ? ek.z : 0.f;
            float m3 = (tij <= tk.w) ? ek.w : 0.f;
            dent += m0 + m1 + m2 + m3;
            denh += ((rij <= rk.x) ? m0 : 0.f) + ((rij <= rk.y) ? m1 : 0.f)
                  + ((rij <= rk.z) ? m2 : 0.f) + ((rij <= rk.w) ? m3 : 0.f);
        }
        pos_t = (double)(l - logf(dent + 1e-7f));
        pos_h = (double)(l - logf(denh + 1e-7f));
    }

    // ---- block reduction (double) ----
    #pragma unroll
    for (int o = 16; o; o >>= 1) {
        pos_t += __shfl_xor_sync(FULL, pos_t, o);
        pos_h += __shfl_xor_sync(FULL, pos_h, o);
    }
    if (lane == 0) { redt[w] = pos_t; redh[w] = pos_h; }
    __syncthreads();

    // ---- global accumulation + last-block finalize (self-resetting) ----
    if (j == 0) {
        double at = 0.0, ah = 0.0;
        #pragma unroll
        for (int ww = 0; ww < NWARP; ww++) { at += redt[ww]; ah += redh[ww]; }
        atomicAdd(&g_acc_trans, at);
        atomicAdd(&g_acc_hard,  ah);
        __threadfence();
        unsigned ticket = atomicAdd(&g_done, 1u);
        if (ticket == (unsigned)(gridDim.x - 1)) {
            double vt = atomicAdd(&g_acc_trans, 0.0);
            double vh = atomicAdd(&g_acc_hard,  0.0);
            const double denom = (double)N * (double)(N - 1);
            out[0] = (float)((-vh / denom) + 0.5 * (-vt / denom));
            // reset for the next invocation / graph replay
            g_acc_trans = 0.0;
            g_acc_hard  = 0.0;
            g_done      = 0u;
        }
    }
}

extern "C" void kernel_launch(void* const* d_in, const int* in_sizes, int n_in,
                              void* d_out, int out_size) {
    const float* feat   = (const float*)d_in[0];
    const float* rgreen = (const float*)d_in[1];
    const float* rred   = (const float*)d_in[2];
    const float* trans  = (const float*)d_in[3];
    const int*   sym    = (const int*)d_in[4];
    float* out = (float*)d_out;

    rnc_main_kernel<<<N, N>>>(feat, rgreen, rred, trans, sym, out);
}

// round 5
// speedup vs baseline: 1.5543x; 1.0141x over previous
#include <cuda_runtime.h>
#include <math.h>

#define N 384
#define D 128
#define TPB 192            // 2 j per thread
#define NWARP (TPB / 32)   // 6
#define FULL 0xFFFFFFFFu

// Persistent accumulators. Zero at load; last block resets after finalizing so
// every invocation (correctness run + each graph replay) starts clean.
__device__ double   g_acc_trans = 0.0;
__device__ double   g_acc_hard  = 0.0;
__device__ unsigned g_done      = 0u;

__global__ __launch_bounds__(TPB) void rnc_main_kernel(
    const float* __restrict__ feat,   // [N, D]
    const float* __restrict__ rgreen, // [N, 3]
    const float* __restrict__ rred,   // [N, 3]
    const float* __restrict__ trans,  // [N, 3]
    const int*   __restrict__ sym,    // [N, 1]
    float*       __restrict__ out)
{
    __shared__ __align__(16) float fi[D];
    __shared__ __align__(16) float td_sh[N];
    __shared__ __align__(16) float rd_sh[N];
    __shared__ __align__(16) float e_sh[N];
    __shared__ double redt[NWARP];
    __shared__ double redh[NWARP];

    const int i    = blockIdx.x;
    const int tid  = threadIdx.x;
    const int lane = tid & 31;
    const int w    = tid >> 5;
    const int j0   = tid;        // first column this thread owns
    const int j1   = tid + TPB;  // second column

    // ---- stage row-i feature vector in shared (coalesced) ----
    if (tid < D / 4)
        reinterpret_cast<float4*>(fi)[tid] =
            reinterpret_cast<const float4*>(feat + i * D)[tid];
    __syncthreads();

    // ---- feature squared distances, warp-cooperative & coalesced ----
    // Pass 0: warp w covers rows [32w, 32w+32)   -> lane r keeps row = its j0.
    // Pass 1: warp w covers rows [192+32w, ...)  -> lane r keeps row = its j1.
    float sq0 = 0.f, sq1 = 0.f;
    {
        const float4 a = reinterpret_cast<const float4*>(fi)[lane];
        #pragma unroll 1
        for (int pass = 0; pass < 2; pass++) {
            const int rowbase = pass * TPB + w * 32;
            #pragma unroll 4
            for (int r = 0; r < 32; r++) {
                float4 b = reinterpret_cast<const float4*>(feat + (rowbase + r) * D)[lane];
                float d0 = a.x - b.x, d1 = a.y - b.y, d2 = a.z - b.z, d3 = a.w - b.w;
                float p = d0 * d0;
                p = fmaf(d1, d1, p);
                p = fmaf(d2, d2, p);
                p = fmaf(d3, d3, p);
                #pragma unroll
                for (int o = 16; o; o >>= 1) p += __shfl_xor_sync(FULL, p, o);
                if (lane == r) { if (pass == 0) sq0 = p; else sq1 = p; }
            }
        }
    }
    // rowmax of logits is exactly 0: logit_ii = -0.5*sqrt(0) = 0 bit-exactly
    // (same memory subtracted from itself) and every other logit <= 0.
    float l0 = -((sq0 > 0.f) ? sqrtf(sq0) : 0.f) * 0.5f;
    float l1 = -((sq1 > 0.f) ? sqrtf(sq1) : 0.f) * 0.5f;

    // ---- label diffs for both columns ----
    float td0, td1, rd0, rd1;
    {
        float ti0 = trans[i*3+0], ti1 = trans[i*3+1], ti2 = trans[i*3+2]; // broadcast
        #pragma unroll
        for (int h = 0; h < 2; h++) {
            int j = h ? j1 : j0;
            float d0 = ti0 - trans[j*3+0];
            float d1 = ti1 - trans[j*3+1];
            float d2 = ti2 - trans[j*3+2];
            float a0 = fabsf(d0), a1 = fabsf(d1), a2 = fabsf(d2);
            float s = ((a0 < 1.f) ? 0.5f*d0*d0 : a0 - 0.5f)
                    + ((a1 < 1.f) ? 0.5f*d1*d1 : a1 - 0.5f)
                    + ((a2 < 1.f) ? 0.5f*d2*d2 : a2 - 0.5f);
            float tv = s * (1.0f / 3.0f);
            if (h) td1 = tv; else td0 = tv;
        }

        const float EPSC = 1e-8f;
        float gi0 = rgreen[i*3+0], gi1 = rgreen[i*3+1], gi2 = rgreen[i*3+2];
        float ngi = fmaxf(sqrtf(gi0*gi0 + gi1*gi1 + gi2*gi2), EPSC);
        float ri0 = rred[i*3+0], ri1 = rred[i*3+1], ri2 = rred[i*3+2];
        float nri = fmaxf(sqrtf(ri0*ri0 + ri1*ri1 + ri2*ri2), EPSC);
        int   si  = sym[i];
        #pragma unroll
        for (int h = 0; h < 2; h++) {
            int j = h ? j1 : j0;
            float gj0 = rgreen[j*3+0], gj1 = rgreen[j*3+1], gj2 = rgreen[j*3+2];
            float ngj = fmaxf(sqrtf(gj0*gj0 + gj1*gj1 + gj2*gj2), EPSC);
            float gd  = 1.0f - (gi0*gj0 + gi1*gj1 + gi2*gj2) / (ngi * ngj);
            float rj0 = rred[j*3+0], rj1 = rred[j*3+1], rj2 = rred[j*3+2];
            float nrj = fmaxf(sqrtf(rj0*rj0 + rj1*rj1 + rj2*rj2), EPSC);
            float rdd = 1.0f - (ri0*rj0 + ri1*rj1 + ri2*rj2) / (nri * nrj);
            bool psym = (si == 1) || (sym[j] == 1);
            float rv = psym ? gd : gd + rdd;
            if (h) rd1 = rv; else rd0 = rv;
        }
    }

    td_sh[j0] = td0;  td_sh[j1] = td1;
    rd_sh[j0] = rd0;  rd_sh[j1] = rd1;
    e_sh[j0] = (j0 == i) ? 0.f : expf(l0);  // zero diag weight == offdiag einsum
    e_sh[j1] = (j1 == i) ? 0.f : expf(l1);
    __syncthreads();

    // ---- masked denominators: float4 broadcast loads amortized over 2 j ----
    float dent0 = 0.f, denh0 = 0.f, dent1 = 0.f, denh1 = 0.f;
    {
        const float4* td4 = reinterpret_cast<const float4*>(td_sh);
        const float4* rd4 = reinterpret_cast<const float4*>(rd_sh);
        const float4* e4  = reinterpret_cast<const float4*>(e_sh);
        #pragma unroll 2
        for (int k4 = 0; k4 < N / 4; k4++) {
            float4 tk = td4[k4];
            float4 rk = rd4[k4];
            float4 ek = e4[k4];
            if (td0 <= tk.x) { dent0 += ek.x; if (rd0 <= rk.x) denh0 += ek.x; }
            if (td0 <= tk.y) { dent0 += ek.y; if (rd0 <= rk.y) denh0 += ek.y; }
            if (td0 <= tk.z) { dent0 += ek.z; if (rd0 <= rk.z) denh0 += ek.z; }
            if (td0 <= tk.w) { dent0 += ek.w; if (rd0 <= rk.w) denh0 += ek.w; }
            if (td1 <= tk.x) { dent1 += ek.x; if (rd1 <= rk.x) denh1 += ek.x; }
            if (td1 <= tk.y) { dent1 += ek.y; if (rd1 <= rk.y) denh1 += ek.y; }
            if (td1 <= tk.z) { dent1 += ek.z; if (rd1 <= rk.z) denh1 += ek.z; }
            if (td1 <= tk.w) { dent1 += ek.w; if (rd1 <= rk.w) denh1 += ek.w; }
        }
    }

    double pos_t = 0.0, pos_h = 0.0;
    if (j0 != i) {
        pos_t += (double)(l0 - logf(dent0 + 1e-7f));
        pos_h += (double)(l0 - logf(denh0 + 1e-7f));
    }
    if (j1 != i) {
        pos_t += (double)(l1 - logf(dent1 + 1e-7f));
        pos_h += (double)(l1 - logf(denh1 + 1e-7f));
    }

    // ---- block reduction (double) ----
    #pragma unroll
    for (int o = 16; o; o >>= 1) {
        pos_t += __shfl_xor_sync(FULL, pos_t, o);
        pos_h += __shfl_xor_sync(FULL, pos_h, o);
    }
    if (lane == 0) { redt[w] = pos_t; redh[w] = pos_h; }
    __syncthreads();

    // ---- global accumulation + last-block finalize (self-resetting) ----
    if (tid == 0) {
        double at = 0.0, ah = 0.0;
        #pragma unroll
        for (int ww = 0; ww < NWARP; ww++) { at += redt[ww]; ah += redh[ww]; }
        atomicAdd(&g_acc_trans, at);
        atomicAdd(&g_acc_hard,  ah);
        __threadfence();
        unsigned ticket = atomicAdd(&g_done, 1u);
        if (ticket == (unsigned)(gridDim.x - 1)) {
            double vt = atomicAdd(&g_acc_trans, 0.0);
            double vh = atomicAdd(&g_acc_hard,  0.0);
            const double denom = (double)N * (double)(N - 1);
            out[0] = (float)((-vh / denom) + 0.5 * (-vt / denom));
            g_acc_trans = 0.0;
            g_acc_hard  = 0.0;
            g_done      = 0u;
        }
    }
}

extern "C" void kernel_launch(void* const* d_in, const int* in_sizes, int n_in,
                              void* d_out, int out_size) {
    const float* feat   = (const float*)d_in[0];
    const float* rgreen = (const float*)d_in[1];
    const float* rred   = (const float*)d_in[2];
    const float* trans  = (const float*)d_in[3];
    const int*   sym    = (const int*)d_in[4];
    float* out = (float*)d_out;

    rnc_main_kernel<<<N, TPB>>>(feat, rgreen, rred, trans, sym, out);
}